// round 2
// baseline (speedup 1.0000x reference)
#include <cuda_runtime.h>
#include <cstdint>

#define Hh 2048
#define Ww 2048
#define NPIX (Hh*Ww)            // 4194304
#define BIGL NPIX               // background label
#define NLBL (NPIX+1)
#define KTOP 16
#define NBLK_TOP 120
#define MINSZ 64

// ---------------- device scratch (no allocations allowed) ----------------
__device__ float g_feat1[(size_t)32*NPIX];     // 512 MB, layout [c][y][x]
__device__ int   g_labA[NPIX];
__device__ int   g_labB[NPIX];
__device__ unsigned char g_maskbuf[NPIX];
__device__ int   g_counts[NLBL];
__device__ unsigned long long g_cand[NBLK_TOP*KTOP];
__device__ int   g_lids[KTOP];
__device__ int   g_cnts[KTOP];
__device__ int   g_bbox[KTOP][4];              // y0,y1,x0,x1
__device__ int   g_cls[KTOP];
__device__ float g_roi[KTOP*227*227];
__device__ float g_h1[KTOP*16*56*56];
__device__ float g_h2[KTOP*32*27*27];

// ---------------- conv1: 1->32, 3x3 SAME, relu ----------------
__global__ void k_conv1(const float* __restrict__ x, const float* __restrict__ w1){
    __shared__ float sw[288];
    int tid = threadIdx.x;
    for (int i = tid; i < 288; i += 256) sw[i] = w1[i];
    __syncthreads();
    int p = blockIdx.x*256 + tid;
    int y = p >> 11, xx = p & 2047;
    float v[9];
    #pragma unroll
    for (int ky = 0; ky < 3; ky++)
        #pragma unroll
        for (int kx = 0; kx < 3; kx++){
            int gy = y+ky-1, gx = xx+kx-1;
            v[ky*3+kx] = ((unsigned)gy < 2048u && (unsigned)gx < 2048u) ? x[(gy<<11)+gx] : 0.f;
        }
    #pragma unroll
    for (int oc = 0; oc < 32; oc++){
        float a = 0.f;
        #pragma unroll
        for (int t = 0; t < 9; t++) a += v[t]*sw[oc*9+t];
        g_feat1[((size_t)oc<<22) + p] = fmaxf(a, 0.f);
    }
}

// ---------------- conv2(3x3 SAME relu) fused with conv3(1x1)+sigmoid>0.5 ----------------
// tile 32x8 pixels, 256 threads, 1 pixel x 32 oc per thread; ic processed in 4 groups of 8
__global__ void k_conv23(const float* __restrict__ w2, const float* __restrict__ w3){
    __shared__ __align__(16) float sIn[8*10*34];   // [ic8][y0..9][x0..33]
    __shared__ __align__(16) float sW[8*9*32];     // [ic8][tap][oc]
    __shared__ float sW3[32];
    int tx = threadIdx.x, ty = threadIdx.y;
    int tid = ty*32 + tx;
    if (tid < 32) sW3[tid] = w3[tid];
    int x0 = blockIdx.x*32 - 1, y0 = blockIdx.y*8 - 1;
    float acc[32];
    #pragma unroll
    for (int i = 0; i < 32; i++) acc[i] = 0.f;

    for (int g = 0; g < 4; g++){
        if (g) __syncthreads();
        // load input tile for this ic group (zero-padded)
        for (int i = tid; i < 8*10*34; i += 256){
            int ic = i/340, r = i%340, yy = r/34, xxv = r%34;
            int gy = y0+yy, gx = x0+xxv;
            float v = 0.f;
            if ((unsigned)gy < 2048u && (unsigned)gx < 2048u)
                v = g_feat1[(((size_t)(g*8+ic))<<22) + (gy<<11) + gx];
            sIn[i] = v;
        }
        // load weights for this ic group, transposed to [ic8][tap][oc]
        for (int i = tid; i < 8*9*32; i += 256){
            int ic8 = i/288, tap = (i%288)/32, oc = i%32;
            sW[i] = w2[((size_t)oc*32 + (g*8+ic8))*9 + tap];
        }
        __syncthreads();
        for (int ic = 0; ic < 8; ic++){
            const float* bi = sIn + ic*340 + ty*34 + tx;
            #pragma unroll
            for (int t = 0; t < 9; t++){
                float v = bi[(t/3)*34 + (t%3)];
                const float4* wv = (const float4*)(sW + (ic*9+t)*32);  // warp-uniform -> broadcast
                #pragma unroll
                for (int q = 0; q < 8; q++){
                    float4 w = wv[q];
                    acc[q*4+0] += v*w.x; acc[q*4+1] += v*w.y;
                    acc[q*4+2] += v*w.z; acc[q*4+3] += v*w.w;
                }
            }
        }
    }
    float z = 0.f;
    #pragma unroll
    for (int oc = 0; oc < 32; oc++) z += fmaxf(acc[oc], 0.f)*sW3[oc];
    int y = blockIdx.y*8 + ty, x = blockIdx.x*32 + tx;
    int p = (y<<11) + x;
    bool m = z > 0.f;                 // sigmoid(z) > 0.5  <=>  z > 0
    g_maskbuf[p] = m ? 1 : 0;
    g_labA[p] = m ? p : BIGL;
}

// ---------------- connected components: 8 exact iterations per launch (halo 8) ----------------
__global__ void k_cc(int ab){
    __shared__ int sA[48*49];
    __shared__ int sB[48*49];
    __shared__ unsigned char sM[48*49];
    const int* __restrict__ src = ab ? g_labB : g_labA;
    int* __restrict__ dst = ab ? g_labA : g_labB;
    int tx = threadIdx.x, ty = threadIdx.y;
    int tid = ty*32 + tx;
    int gx0 = blockIdx.x*32 - 8, gy0 = blockIdx.y*32 - 8;
    for (int i = tid; i < 2304; i += 1024){
        int cy = i/48, cx = i%48;
        int gy = gy0+cy, gx = gx0+cx;
        int v = BIGL; unsigned char m = 0;
        if ((unsigned)gy < 2048u && (unsigned)gx < 2048u){
            int p = (gy<<11)+gx; m = g_maskbuf[p]; v = src[p];
        }
        sA[cy*49+cx] = v; sM[cy*49+cx] = m;
    }
    __syncthreads();
    int* cur = sA; int* nxt = sB;
    for (int s = 0; s < 8; s++){
        for (int i = tid; i < 2304; i += 1024){
            int cy = i/48, cx = i%48;
            int idx = cy*49 + cx;
            int v = BIGL;
            if (sM[idx]){
                v = cur[idx];
                if (cy > 0)  v = min(v, cur[idx-49]);
                if (cy < 47) v = min(v, cur[idx+49]);
                if (cx > 0)  v = min(v, cur[idx-1]);
                if (cx < 47) v = min(v, cur[idx+1]);
            }
            nxt[idx] = v;
        }
        __syncthreads();
        int* t = cur; cur = nxt; nxt = t;
    }
    int gy = gy0+8+ty, gx = gx0+8+tx;
    dst[(gy<<11)+gx] = cur[(ty+8)*49 + (tx+8)];
}

// ---------------- histogram ----------------
__global__ void k_zero_counts(){
    int i = blockIdx.x*1024 + threadIdx.x;
    if (i < NLBL) g_counts[i] = 0;
}
__global__ void k_count(){
    int p = blockIdx.x*256 + threadIdx.x;
    int l = g_labA[p];
    unsigned mk = __match_any_sync(0xffffffffu, l);
    int leader = __ffs(mk) - 1;
    if ((threadIdx.x & 31) == leader && l != BIGL)
        atomicAdd(&g_counts[l], __popc(mk));
}

// ---------------- exact top-16 (count desc, label asc): two-stage ----------------
__global__ void k_topA(){
    __shared__ unsigned long long s[256*16];
    int chunk = (NLBL + NBLK_TOP - 1)/NBLK_TOP;
    int lo = blockIdx.x*chunk;
    int hi = min(NLBL, lo + chunk);
    unsigned long long best[16];
    #pragma unroll
    for (int i = 0; i < 16; i++) best[i] = 0ull;
    unsigned long long bmin = 0ull; int bpos = 0;
    for (int i = lo + threadIdx.x; i < hi; i += 256){
        unsigned long long key = ((unsigned long long)(unsigned)g_counts[i] << 32)
                               | (unsigned)(~(unsigned)i);
        if (key > bmin){
            best[bpos] = key;
            bmin = best[0]; bpos = 0;
            #pragma unroll
            for (int j = 1; j < 16; j++) if (best[j] < bmin){ bmin = best[j]; bpos = j; }
        }
    }
    for (int j = 0; j < 16; j++) s[threadIdx.x*16 + j] = best[j];
    __syncthreads();
    if (threadIdx.x < 32){
        for (int r = 0; r < 16; r++){
            unsigned long long m = 0ull; int mp = -1;
            for (int i = threadIdx.x; i < 4096; i += 32){
                unsigned long long v = s[i];
                if (v > m){ m = v; mp = i; }
            }
            for (int off = 16; off; off >>= 1){
                unsigned long long om = __shfl_down_sync(0xffffffffu, m, off);
                int op = __shfl_down_sync(0xffffffffu, mp, off);
                if (om > m){ m = om; mp = op; }
            }
            m  = __shfl_sync(0xffffffffu, m, 0);
            mp = __shfl_sync(0xffffffffu, mp, 0);
            if (threadIdx.x == 0){
                g_cand[blockIdx.x*16 + r] = m;
                if (mp >= 0) s[mp] = 0ull;
            }
            __syncwarp();
        }
    }
}
__global__ void k_topB(){
    __shared__ unsigned long long s[2048];
    int tid = threadIdx.x;
    for (int i = tid; i < 2048; i += 256) s[i] = (i < NBLK_TOP*16) ? g_cand[i] : 0ull;
    __syncthreads();
    if (tid < 32){
        for (int r = 0; r < 16; r++){
            unsigned long long m = 0ull; int mp = -1;
            for (int i = tid; i < 2048; i += 32){
                unsigned long long v = s[i];
                if (v > m){ m = v; mp = i; }
            }
            for (int off = 16; off; off >>= 1){
                unsigned long long om = __shfl_down_sync(0xffffffffu, m, off);
                int op = __shfl_down_sync(0xffffffffu, mp, off);
                if (om > m){ m = om; mp = op; }
            }
            m  = __shfl_sync(0xffffffffu, m, 0);
            mp = __shfl_sync(0xffffffffu, mp, 0);
            if (tid == 0){
                g_cnts[r] = (int)(m >> 32);
                g_lids[r] = (int)(~(unsigned)(m & 0xffffffffull));
                if (mp >= 0) s[mp] = 0ull;
            }
            __syncwarp();
        }
    }
}

// ---------------- bounding boxes ----------------
__global__ void k_bbinit(){
    int k = threadIdx.x;
    if (k < 16){ g_bbox[k][0] = 0x7FFFFFFF; g_bbox[k][1] = -1; g_bbox[k][2] = 0x7FFFFFFF; g_bbox[k][3] = -1; }
}
__global__ void k_bbox(){
    __shared__ int slid[16];
    __shared__ int sbb[16][4];
    int tid = threadIdx.x;
    if (tid < 16){
        slid[tid] = g_lids[tid];
        sbb[tid][0] = 0x7FFFFFFF; sbb[tid][1] = -1; sbb[tid][2] = 0x7FFFFFFF; sbb[tid][3] = -1;
    }
    __syncthreads();
    int base = blockIdx.x*1024;
    for (int q = 0; q < 4; q++){
        int p = base + q*256 + tid;
        int l = g_labA[p];
        if (l != BIGL){
            int y = p >> 11, x = p & 2047;
            #pragma unroll
            for (int k = 0; k < 16; k++) if (l == slid[k]){
                if (y < sbb[k][0]) atomicMin(&sbb[k][0], y);
                if (y > sbb[k][1]) atomicMax(&sbb[k][1], y);
                if (x < sbb[k][2]) atomicMin(&sbb[k][2], x);
                if (x > sbb[k][3]) atomicMax(&sbb[k][3], x);
            }
        }
    }
    __syncthreads();
    if (tid < 16 && sbb[tid][0] != 0x7FFFFFFF){
        atomicMin(&g_bbox[tid][0], sbb[tid][0]);
        atomicMax(&g_bbox[tid][1], sbb[tid][1]);
        atomicMin(&g_bbox[tid][2], sbb[tid][2]);
        atomicMax(&g_bbox[tid][3], sbb[tid][3]);
    }
}

// ---------------- ROI bilinear resize (227x227) ----------------
__global__ void k_roi(const float* __restrict__ img){
    int k = blockIdx.x;
    int y0 = g_bbox[k][0], y1 = g_bbox[k][1], x0 = g_bbox[k][2], x1 = g_bbox[k][3];
    if (y0 == 0x7FFFFFFF){ y0 = 0; y1 = 2047; x0 = 0; x1 = 2047; }  // empty comp: argmax(all-false)=0
    float dy = (float)(y1 - y0), dx = (float)(x1 - x0);
    for (int idx = threadIdx.x; idx < 227*227; idx += blockDim.x){
        int i = idx/227, j = idx%227;
        float gy = (float)y0 + ((float)i/226.0f)*dy;
        float gx = (float)x0 + ((float)j/226.0f)*dx;
        int yf = min(max((int)floorf(gy), 0), 2046);
        int xf = min(max((int)floorf(gx), 0), 2046);
        float fy = gy - (float)yf, fx = gx - (float)xf;
        const float* r0 = img + (yf<<11) + xf;
        float v00 = r0[0], v01 = r0[1], v10 = r0[2048], v11 = r0[2049];
        g_roi[k*51529 + idx] = (1.f-fy)*((1.f-fx)*v00 + fx*v01) + fy*((1.f-fx)*v10 + fx*v11);
    }
}

// ---------------- classifier conv1: 7x7 s4 VALID, 1->16, relu ----------------
__global__ void k_c1(const float* __restrict__ cw1){
    __shared__ float sw[784];
    int tid = threadIdx.x;
    for (int i = tid; i < 784; i += 256) sw[i] = cw1[i];
    __syncthreads();
    int o = blockIdx.x*256 + tid;           // 16*16*56*56 = 802816 total, divides evenly
    int k = o/50176, r = o%50176, oc = r/3136, s = r%3136, oy = s/56, ox = s%56;
    const float* roi = g_roi + k*51529;
    const float* wb = sw + oc*49;
    float a = 0.f;
    #pragma unroll
    for (int ky = 0; ky < 7; ky++){
        const float* rr = roi + (oy*4+ky)*227 + ox*4;
        #pragma unroll
        for (int kx = 0; kx < 7; kx++) a += rr[kx]*wb[ky*7+kx];
    }
    g_h1[o] = fmaxf(a, 0.f);
}

// ---------------- classifier conv2: 3x3 s2 VALID, 16->32, relu ----------------
__global__ void k_c2(const float* __restrict__ cw2){
    __shared__ float sw[4608];
    int tid = threadIdx.x;
    for (int i = tid; i < 4608; i += 256) sw[i] = cw2[i];
    __syncthreads();
    int o = blockIdx.x*256 + tid;           // 16*32*27*27 = 373248, divides evenly
    int k = o/23328, r = o%23328, oc = r/729, s = r%729, oy = s/27, ox = s%27;
    const float* h = g_h1 + (size_t)k*16*3136;
    float a = 0.f;
    for (int ic = 0; ic < 16; ic++){
        const float* hb = h + ic*3136 + (oy*2)*56 + ox*2;
        const float* wb = sw + (oc*16+ic)*9;
        #pragma unroll
        for (int ky = 0; ky < 3; ky++)
            #pragma unroll
            for (int kx = 0; kx < 3; kx++)
                a += hb[ky*56+kx]*wb[ky*3+kx];
    }
    g_h2[o] = fmaxf(a, 0.f);
}

// ---------------- global mean + fc + argmax (deterministic warp reductions) ----------------
__global__ void k_cls(const float* __restrict__ fc){
    __shared__ float ssum[32];
    int k = blockIdx.x;
    int tid = threadIdx.x, w = tid >> 5, lane = tid & 31;
    for (int oc = w*4; oc < w*4+4; oc++){
        float s = 0.f;
        const float* h = g_h2 + ((size_t)(k*32+oc))*729;
        for (int i = lane; i < 729; i += 32) s += h[i];
        for (int off = 16; off; off >>= 1) s += __shfl_down_sync(0xffffffffu, s, off);
        if (lane == 0) ssum[oc] = s;
    }
    __syncthreads();
    if (tid == 0){
        float best = -1e30f; int bc = 0;
        for (int c = 0; c < 4; c++){
            float lg = 0.f;
            for (int oc = 0; oc < 32; oc++) lg += (ssum[oc]*(1.0f/729.0f))*fc[oc*4+c];
            if (lg > best){ best = lg; bc = c; }
        }
        g_cls[k] = bc;
    }
}

// ---------------- final mask composition ----------------
__global__ void k_final(float* __restrict__ out){
    __shared__ int slid[16], scnt[16], scls[16];
    int tid = threadIdx.x;
    if (tid < 16){ slid[tid] = g_lids[tid]; scnt[tid] = g_cnts[tid]; scls[tid] = g_cls[tid]; }
    __syncthreads();
    int p = blockIdx.x*256 + tid;
    int l = g_labA[p];
    float o0 = 0.f, o1 = 0.f, o2 = 0.f, o3 = 0.f;
    #pragma unroll
    for (int k = 0; k < 16; k++){
        if (scnt[k] >= MINSZ && slid[k] == l){
            int c = scls[k];
            if (c == 0) o0 = 1.f; else if (c == 1) o1 = 1.f; else if (c == 2) o2 = 1.f; else o3 = 1.f;
        }
    }
    out[p] = o0;
    out[NPIX + p] = o1;
    out[2*NPIX + p] = o2;
    out[3*NPIX + p] = o3;
}

// ---------------- launch ----------------
extern "C" void kernel_launch(void* const* d_in, const int* in_sizes, int n_in,
                              void* d_out, int out_size){
    const float *x = nullptr, *w1 = nullptr, *w2 = nullptr, *w3 = nullptr;
    const float *cw1 = nullptr, *cw2 = nullptr, *fc = nullptr;
    for (int i = 0; i < n_in; i++){
        switch (in_sizes[i]){
            case 4194304: x   = (const float*)d_in[i]; break;
            case 288:     w1  = (const float*)d_in[i]; break;
            case 9216:    w2  = (const float*)d_in[i]; break;
            case 32:      w3  = (const float*)d_in[i]; break;
            case 784:     cw1 = (const float*)d_in[i]; break;
            case 4608:    cw2 = (const float*)d_in[i]; break;
            case 128:     fc  = (const float*)d_in[i]; break;
            default: break;
        }
    }
    float* out = (float*)d_out;

    k_conv1<<<NPIX/256, 256>>>(x, w1);
    k_conv23<<<dim3(64,256), dim3(32,8)>>>(w2, w3);

    for (int i = 0; i < 4; i++){
        k_cc<<<dim3(64,64), dim3(32,32)>>>(0);   // A -> B
        k_cc<<<dim3(64,64), dim3(32,32)>>>(1);   // B -> A
    }

    k_zero_counts<<<(NLBL+1023)/1024, 1024>>>();
    k_count<<<NPIX/256, 256>>>();
    k_topA<<<NBLK_TOP, 256>>>();
    k_topB<<<1, 256>>>();

    k_bbinit<<<1, 16>>>();
    k_bbox<<<NPIX/1024, 256>>>();

    k_roi<<<16, 256>>>(x);
    k_c1<<<802816/256, 256>>>(cw1);
    k_c2<<<373248/256, 256>>>(cw2);
    k_cls<<<16, 256>>>(fc);

    k_final<<<NPIX/256, 256>>>(out);
}

// round 3
// speedup vs baseline: 1.1952x; 1.1952x over previous
#include <cuda_runtime.h>
#include <cstdint>

#define Hh 2048
#define Ww 2048
#define NPIX (Hh*Ww)            // 4194304
#define BIGL NPIX               // background label
#define NLBL (NPIX+1)
#define KTOP 16
#define NBLK_TOP 120
#define MINSZ 64

// ---------------- device scratch (no allocations allowed) ----------------
__device__ int   g_labA[NPIX];
__device__ int   g_labB[NPIX];
__device__ int   g_counts[NLBL];
__device__ unsigned long long g_cand[NBLK_TOP*KTOP];
__device__ int   g_lids[KTOP];
__device__ int   g_cnts[KTOP];
__device__ int   g_bbox[KTOP][4];              // y0,y1,x0,x1
__device__ int   g_cls[KTOP];
__device__ float g_roi[KTOP*227*227];
__device__ float g_h1[KTOP*16*56*56];
__device__ float g_h2[KTOP*32*27*27];

// ================= fused conv1(3x3 relu) + conv2(3x3 relu) + conv3(1x1) + threshold =================
// block: 32x8 threads -> 32x8 output pixels. Dynamic shared:
//   sF  [32][10][34]  feat1 tile (halo 1)         10880 floats
//   sW2 [ic][tap][oc]                              9216 floats
//   sX  [12][37]      input tile (halo 2)            444 floats
//   sW1 [288], sW3[32]
#define SM_SF   0
#define SM_SW2  10880
#define SM_SX   20096
#define SM_SW1  20540
#define SM_SW3  20828
#define SM_TOTAL_F (20860*4)

__global__ __launch_bounds__(256) void k_conv123(const float* __restrict__ x,
                                                 const float* __restrict__ w1,
                                                 const float* __restrict__ w2,
                                                 const float* __restrict__ w3){
    extern __shared__ float sm[];
    float* sF  = sm + SM_SF;
    float* sW2 = sm + SM_SW2;
    float* sX  = sm + SM_SX;
    float* sW1 = sm + SM_SW1;
    float* sW3 = sm + SM_SW3;

    int tx = threadIdx.x, ty = threadIdx.y;
    int tid = ty*32 + tx;

    for (int i = tid; i < 288; i += 256) sW1[i] = w1[i];
    for (int i = tid; i < 9216; i += 256){
        int oc = i/288, r = i%288, ic = r/9, tap = r%9;
        sW2[(ic*9+tap)*32 + oc] = w2[i];
    }
    if (tid < 32) sW3[tid] = w3[tid];

    int bx0 = blockIdx.x*32, by0 = blockIdx.y*8;

    // input tile 12x36, origin (by0-2, bx0-2), stride 37
    for (int i = tid; i < 12*36; i += 256){
        int yy = i/36, xxv = i%36;
        int gy = by0-2+yy, gx = bx0-2+xxv;
        float v = 0.f;
        if ((unsigned)gy < 2048u && (unsigned)gx < 2048u) v = x[(gy<<11)+gx];
        sX[yy*37 + xxv] = v;
    }
    __syncthreads();

    // conv1: feat1 for 10x34 region, origin (by0-1, bx0-1)
    for (int i = tid; i < 340; i += 256){
        int fy = i/34, fx = i%34;
        const float* base = sX + fy*37 + fx;     // x row for feat row fy starts at fy (offset -2 vs -1)
        float v[9];
        #pragma unroll
        for (int ky = 0; ky < 3; ky++)
            #pragma unroll
            for (int kx = 0; kx < 3; kx++) v[ky*3+kx] = base[ky*37+kx];
        #pragma unroll
        for (int oc = 0; oc < 32; oc++){
            float a = 0.f;
            #pragma unroll
            for (int t = 0; t < 9; t++) a = fmaf(v[t], sW1[oc*9+t], a);
            sF[oc*340 + i] = fmaxf(a, 0.f);
        }
    }
    __syncthreads();

    // conv2: 32 oc as 16 packed f32x2 accumulators
    unsigned long long acc2[16];
    #pragma unroll
    for (int q = 0; q < 16; q++) acc2[q] = 0ull;

    for (int ic = 0; ic < 32; ic++){
        const float* bi = sF + ic*340 + ty*34 + tx;
        #pragma unroll
        for (int t = 0; t < 9; t++){
            float v = bi[(t/3)*34 + (t%3)];
            unsigned long long vv;
            asm("mov.b64 %0, {%1, %1};" : "=l"(vv) : "f"(v));
            const unsigned long long* wv = (const unsigned long long*)(sW2 + (ic*9+t)*32);
            #pragma unroll
            for (int q = 0; q < 16; q++){
                asm("fma.rn.f32x2 %0, %1, %2, %0;" : "+l"(acc2[q]) : "l"(vv), "l"(wv[q]));
            }
        }
    }

    // relu + 1x1 conv + threshold (sigmoid(z)>0.5 <=> z>0), same accumulation order as before
    float z = 0.f;
    #pragma unroll
    for (int q = 0; q < 16; q++){
        float lo, hi;
        asm("mov.b64 {%0, %1}, %2;" : "=f"(lo), "=f"(hi) : "l"(acc2[q]));
        z += fmaxf(lo, 0.f)*sW3[2*q];
        z += fmaxf(hi, 0.f)*sW3[2*q+1];
    }
    int y = by0 + ty, xp = bx0 + tx;
    int p = (y<<11) + xp;
    g_labA[p] = (z > 0.f) ? p : BIGL;
}

// ================= connected components: 8 exact Jacobi iterations per launch =================
// 64x64 interior tile, halo 8 -> 80x80 region, 1024 threads, 2 ping-pong buffers in dyn smem.
// mask == (lab != BIGL) is an invariant of min-propagation, so no separate mask array.
#define CC_SMEM (2*6400*4)
__global__ __launch_bounds__(1024) void k_cc(const int* __restrict__ src, int* __restrict__ dst){
    extern __shared__ int sh[];
    int* A = sh;
    int* B = sh + 6400;
    int tx = threadIdx.x, ty = threadIdx.y;
    int gx0 = blockIdx.x*64 - 8, gy0 = blockIdx.y*64 - 8;

    #pragma unroll
    for (int a = 0; a < 3; a++){
        int cy = ty + a*32;
        #pragma unroll
        for (int b = 0; b < 3; b++){
            int cx = tx + b*32;
            if (cy < 80 && cx < 80){
                int gy = gy0 + cy, gx = gx0 + cx;
                int v = BIGL;
                if ((unsigned)gy < 2048u && (unsigned)gx < 2048u) v = src[(gy<<11)+gx];
                A[cy*80 + cx] = v;
            }
        }
    }
    __syncthreads();

    int* cur = A; int* nxt = B;
    for (int s = 0; s < 8; s++){
        #pragma unroll
        for (int a = 0; a < 3; a++){
            int cy = ty + a*32;
            #pragma unroll
            for (int b = 0; b < 3; b++){
                int cx = tx + b*32;
                if (cy < 80 && cx < 80){
                    int idx = cy*80 + cx;
                    int c = cur[idx];
                    int v = BIGL;
                    if (c != BIGL){
                        v = c;
                        if (cy > 0)  v = min(v, cur[idx-80]);
                        if (cy < 79) v = min(v, cur[idx+80]);
                        if (cx > 0)  v = min(v, cur[idx-1]);
                        if (cx < 79) v = min(v, cur[idx+1]);
                    }
                    nxt[idx] = v;
                }
            }
        }
        __syncthreads();
        int* t = cur; cur = nxt; nxt = t;
    }

    #pragma unroll
    for (int a = 0; a < 2; a++){
        int cy = ty + 8 + a*32;
        #pragma unroll
        for (int b = 0; b < 2; b++){
            int cx = tx + 8 + b*32;
            int gy = gy0 + cy, gx = gx0 + cx;
            dst[(gy<<11)+gx] = cur[cy*80 + cx];
        }
    }
}

// ---------------- histogram ----------------
__global__ void k_zero_counts(){
    int i = blockIdx.x*1024 + threadIdx.x;
    if (i < NLBL) g_counts[i] = 0;
}
__global__ void k_count(){
    int p = blockIdx.x*256 + threadIdx.x;
    int l = g_labA[p];
    unsigned mk = __match_any_sync(0xffffffffu, l);
    int leader = __ffs(mk) - 1;
    if ((threadIdx.x & 31) == leader && l != BIGL)
        atomicAdd(&g_counts[l], __popc(mk));
}

// ---------------- exact top-16 (count desc, label asc): two-stage ----------------
__global__ void k_topA(){
    __shared__ unsigned long long s[256*16];
    int chunk = (NLBL + NBLK_TOP - 1)/NBLK_TOP;
    int lo = blockIdx.x*chunk;
    int hi = min(NLBL, lo + chunk);
    unsigned long long best[16];
    #pragma unroll
    for (int i = 0; i < 16; i++) best[i] = 0ull;
    unsigned long long bmin = 0ull; int bpos = 0;
    for (int i = lo + threadIdx.x; i < hi; i += 256){
        unsigned long long key = ((unsigned long long)(unsigned)g_counts[i] << 32)
                               | (unsigned)(~(unsigned)i);
        if (key > bmin){
            best[bpos] = key;
            bmin = best[0]; bpos = 0;
            #pragma unroll
            for (int j = 1; j < 16; j++) if (best[j] < bmin){ bmin = best[j]; bpos = j; }
        }
    }
    for (int j = 0; j < 16; j++) s[threadIdx.x*16 + j] = best[j];
    __syncthreads();
    if (threadIdx.x < 32){
        for (int r = 0; r < 16; r++){
            unsigned long long m = 0ull; int mp = -1;
            for (int i = threadIdx.x; i < 4096; i += 32){
                unsigned long long v = s[i];
                if (v > m){ m = v; mp = i; }
            }
            for (int off = 16; off; off >>= 1){
                unsigned long long om = __shfl_down_sync(0xffffffffu, m, off);
                int op = __shfl_down_sync(0xffffffffu, mp, off);
                if (om > m){ m = om; mp = op; }
            }
            m  = __shfl_sync(0xffffffffu, m, 0);
            mp = __shfl_sync(0xffffffffu, mp, 0);
            if (threadIdx.x == 0){
                g_cand[blockIdx.x*16 + r] = m;
                if (mp >= 0) s[mp] = 0ull;
            }
            __syncwarp();
        }
    }
}
__global__ void k_topB(){
    __shared__ unsigned long long s[2048];
    int tid = threadIdx.x;
    for (int i = tid; i < 2048; i += 256) s[i] = (i < NBLK_TOP*16) ? g_cand[i] : 0ull;
    __syncthreads();
    if (tid < 32){
        for (int r = 0; r < 16; r++){
            unsigned long long m = 0ull; int mp = -1;
            for (int i = tid; i < 2048; i += 32){
                unsigned long long v = s[i];
                if (v > m){ m = v; mp = i; }
            }
            for (int off = 16; off; off >>= 1){
                unsigned long long om = __shfl_down_sync(0xffffffffu, m, off);
                int op = __shfl_down_sync(0xffffffffu, mp, off);
                if (om > m){ m = om; mp = op; }
            }
            m  = __shfl_sync(0xffffffffu, m, 0);
            mp = __shfl_sync(0xffffffffu, mp, 0);
            if (tid == 0){
                g_cnts[r] = (int)(m >> 32);
                g_lids[r] = (int)(~(unsigned)(m & 0xffffffffull));
                if (mp >= 0) s[mp] = 0ull;
            }
            __syncwarp();
        }
    }
}

// ---------------- bounding boxes ----------------
__global__ void k_bbinit(){
    int k = threadIdx.x;
    if (k < 16){ g_bbox[k][0] = 0x7FFFFFFF; g_bbox[k][1] = -1; g_bbox[k][2] = 0x7FFFFFFF; g_bbox[k][3] = -1; }
}
__global__ void k_bbox(){
    __shared__ int slid[16];
    __shared__ int sbb[16][4];
    int tid = threadIdx.x;
    if (tid < 16){
        slid[tid] = g_lids[tid];
        sbb[tid][0] = 0x7FFFFFFF; sbb[tid][1] = -1; sbb[tid][2] = 0x7FFFFFFF; sbb[tid][3] = -1;
    }
    __syncthreads();
    int base = blockIdx.x*1024;
    for (int q = 0; q < 4; q++){
        int p = base + q*256 + tid;
        int l = g_labA[p];
        if (l != BIGL){
            int y = p >> 11, x = p & 2047;
            #pragma unroll
            for (int k = 0; k < 16; k++) if (l == slid[k]){
                if (y < sbb[k][0]) atomicMin(&sbb[k][0], y);
                if (y > sbb[k][1]) atomicMax(&sbb[k][1], y);
                if (x < sbb[k][2]) atomicMin(&sbb[k][2], x);
                if (x > sbb[k][3]) atomicMax(&sbb[k][3], x);
            }
        }
    }
    __syncthreads();
    if (tid < 16 && sbb[tid][0] != 0x7FFFFFFF){
        atomicMin(&g_bbox[tid][0], sbb[tid][0]);
        atomicMax(&g_bbox[tid][1], sbb[tid][1]);
        atomicMin(&g_bbox[tid][2], sbb[tid][2]);
        atomicMax(&g_bbox[tid][3], sbb[tid][3]);
    }
}

// ---------------- ROI bilinear resize (227x227) ----------------
__global__ void k_roi(const float* __restrict__ img){
    int k = blockIdx.x;
    int y0 = g_bbox[k][0], y1 = g_bbox[k][1], x0 = g_bbox[k][2], x1 = g_bbox[k][3];
    if (y0 == 0x7FFFFFFF){ y0 = 0; y1 = 2047; x0 = 0; x1 = 2047; }  // empty comp: argmax(all-false)=0
    float dy = (float)(y1 - y0), dx = (float)(x1 - x0);
    for (int idx = threadIdx.x; idx < 227*227; idx += blockDim.x){
        int i = idx/227, j = idx%227;
        float gy = (float)y0 + ((float)i/226.0f)*dy;
        float gx = (float)x0 + ((float)j/226.0f)*dx;
        int yf = min(max((int)floorf(gy), 0), 2046);
        int xf = min(max((int)floorf(gx), 0), 2046);
        float fy = gy - (float)yf, fx = gx - (float)xf;
        const float* r0 = img + (yf<<11) + xf;
        float v00 = r0[0], v01 = r0[1], v10 = r0[2048], v11 = r0[2049];
        g_roi[k*51529 + idx] = (1.f-fy)*((1.f-fx)*v00 + fx*v01) + fy*((1.f-fx)*v10 + fx*v11);
    }
}

// ---------------- classifier conv1: 7x7 s4 VALID, 1->16, relu ----------------
__global__ void k_c1(const float* __restrict__ cw1){
    __shared__ float sw[784];
    int tid = threadIdx.x;
    for (int i = tid; i < 784; i += 256) sw[i] = cw1[i];
    __syncthreads();
    int o = blockIdx.x*256 + tid;           // 16*16*56*56 = 802816 total, divides evenly
    int k = o/50176, r = o%50176, oc = r/3136, s = r%3136, oy = s/56, ox = s%56;
    const float* roi = g_roi + k*51529;
    const float* wb = sw + oc*49;
    float a = 0.f;
    #pragma unroll
    for (int ky = 0; ky < 7; ky++){
        const float* rr = roi + (oy*4+ky)*227 + ox*4;
        #pragma unroll
        for (int kx = 0; kx < 7; kx++) a += rr[kx]*wb[ky*7+kx];
    }
    g_h1[o] = fmaxf(a, 0.f);
}

// ---------------- classifier conv2: 3x3 s2 VALID, 16->32, relu ----------------
__global__ void k_c2(const float* __restrict__ cw2){
    __shared__ float sw[4608];
    int tid = threadIdx.x;
    for (int i = tid; i < 4608; i += 256) sw[i] = cw2[i];
    __syncthreads();
    int o = blockIdx.x*256 + tid;           // 16*32*27*27 = 373248, divides evenly
    int k = o/23328, r = o%23328, oc = r/729, s = r%729, oy = s/27, ox = s%27;
    const float* h = g_h1 + (size_t)k*16*3136;
    float a = 0.f;
    for (int ic = 0; ic < 16; ic++){
        const float* hb = h + ic*3136 + (oy*2)*56 + ox*2;
        const float* wb = sw + (oc*16+ic)*9;
        #pragma unroll
        for (int ky = 0; ky < 3; ky++)
            #pragma unroll
            for (int kx = 0; kx < 3; kx++)
                a += hb[ky*56+kx]*wb[ky*3+kx];
    }
    g_h2[o] = fmaxf(a, 0.f);
}

// ---------------- global mean + fc + argmax ----------------
__global__ void k_cls(const float* __restrict__ fc){
    __shared__ float ssum[32];
    int k = blockIdx.x;
    int tid = threadIdx.x, w = tid >> 5, lane = tid & 31;
    for (int oc = w*4; oc < w*4+4; oc++){
        float s = 0.f;
        const float* h = g_h2 + ((size_t)(k*32+oc))*729;
        for (int i = lane; i < 729; i += 32) s += h[i];
        for (int off = 16; off; off >>= 1) s += __shfl_down_sync(0xffffffffu, s, off);
        if (lane == 0) ssum[oc] = s;
    }
    __syncthreads();
    if (tid == 0){
        float best = -1e30f; int bc = 0;
        for (int c = 0; c < 4; c++){
            float lg = 0.f;
            for (int oc = 0; oc < 32; oc++) lg += (ssum[oc]*(1.0f/729.0f))*fc[oc*4+c];
            if (lg > best){ best = lg; bc = c; }
        }
        g_cls[k] = bc;
    }
}

// ---------------- final mask composition ----------------
__global__ void k_final(float* __restrict__ out){
    __shared__ int slid[16], scnt[16], scls[16];
    int tid = threadIdx.x;
    if (tid < 16){ slid[tid] = g_lids[tid]; scnt[tid] = g_cnts[tid]; scls[tid] = g_cls[tid]; }
    __syncthreads();
    int p = blockIdx.x*256 + tid;
    int l = g_labA[p];
    float o0 = 0.f, o1 = 0.f, o2 = 0.f, o3 = 0.f;
    #pragma unroll
    for (int k = 0; k < 16; k++){
        if (scnt[k] >= MINSZ && slid[k] == l){
            int c = scls[k];
            if (c == 0) o0 = 1.f; else if (c == 1) o1 = 1.f; else if (c == 2) o2 = 1.f; else o3 = 1.f;
        }
    }
    out[p] = o0;
    out[NPIX + p] = o1;
    out[2*NPIX + p] = o2;
    out[3*NPIX + p] = o3;
}

// ---------------- launch ----------------
extern "C" void kernel_launch(void* const* d_in, const int* in_sizes, int n_in,
                              void* d_out, int out_size){
    const float *x = nullptr, *w1 = nullptr, *w2 = nullptr, *w3 = nullptr;
    const float *cw1 = nullptr, *cw2 = nullptr, *fc = nullptr;
    for (int i = 0; i < n_in; i++){
        switch (in_sizes[i]){
            case 4194304: x   = (const float*)d_in[i]; break;
            case 288:     w1  = (const float*)d_in[i]; break;
            case 9216:    w2  = (const float*)d_in[i]; break;
            case 32:      w3  = (const float*)d_in[i]; break;
            case 784:     cw1 = (const float*)d_in[i]; break;
            case 4608:    cw2 = (const float*)d_in[i]; break;
            case 128:     fc  = (const float*)d_in[i]; break;
            default: break;
        }
    }
    float* out = (float*)d_out;

    // raise dynamic smem limits (idempotent; not a stream op, safe under capture)
    cudaFuncSetAttribute(k_conv123, cudaFuncAttributeMaxDynamicSharedMemorySize, SM_TOTAL_F);
    cudaFuncSetAttribute(k_cc, cudaFuncAttributeMaxDynamicSharedMemorySize, CC_SMEM);

    k_conv123<<<dim3(64,256), dim3(32,8), SM_TOTAL_F>>>(x, w1, w2, w3);

    int* la = nullptr; int* lb = nullptr;
    cudaGetSymbolAddress((void**)&la, g_labA);
    cudaGetSymbolAddress((void**)&lb, g_labB);
    for (int i = 0; i < 4; i++){
        k_cc<<<dim3(32,32), dim3(32,32), CC_SMEM>>>(la, lb);   // A -> B
        k_cc<<<dim3(32,32), dim3(32,32), CC_SMEM>>>(lb, la);   // B -> A
    }

    k_zero_counts<<<(NLBL+1023)/1024, 1024>>>();
    k_count<<<NPIX/256, 256>>>();
    k_topA<<<NBLK_TOP, 256>>>();
    k_topB<<<1, 256>>>();

    k_bbinit<<<1, 16>>>();
    k_bbox<<<NPIX/1024, 256>>>();

    k_roi<<<16, 256>>>(x);
    k_c1<<<802816/256, 256>>>(cw1);
    k_c2<<<373248/256, 256>>>(cw2);
    k_cls<<<16, 256>>>(fc);

    k_final<<<NPIX/256, 256>>>(out);
}

// round 4
// speedup vs baseline: 2.0727x; 1.7342x over previous
#include <cuda_runtime.h>
#include <cstdint>

#define Hh 2048
#define Ww 2048
#define NPIX (Hh*Ww)            // 4194304
#define BIGL NPIX               // background label
#define NLBL (NPIX+1)
#define KTOP 16
#define NBLK_TOP 120
#define MINSZ 64

// ---------------- device scratch (no allocations allowed) ----------------
__device__ int   g_labA[NPIX];
__device__ int   g_labB[NPIX];
__device__ int   g_counts[NLBL];
__device__ unsigned long long g_cand[NBLK_TOP*KTOP];
__device__ int   g_lids[KTOP];
__device__ int   g_cnts[KTOP];
__device__ int   g_bbox[KTOP][4];              // y0,y1,x0,x1
__device__ int   g_cls[KTOP];
__device__ float g_roi[KTOP*227*227];
__device__ float g_h1[KTOP*16*56*56];
__device__ float g_h2[KTOP*32*27*27];

// ---------------- f32x2 helpers ----------------
__device__ __forceinline__ unsigned long long pack2(float v){
    unsigned long long r; asm("mov.b64 %0, {%1, %1};" : "=l"(r) : "f"(v)); return r;
}
__device__ __forceinline__ void fma2(unsigned long long& a, unsigned long long v, unsigned long long w){
    asm("fma.rn.f32x2 %0, %1, %2, %0;" : "+l"(a) : "l"(v), "l"(w));
}
__device__ __forceinline__ float2 unpack2(unsigned long long a){
    float2 f; asm("mov.b64 {%0, %1}, %2;" : "=f"(f.x), "=f"(f.y) : "l"(a)); return f;
}

// ================= fused conv1+conv2+conv3+threshold, 4 px/thread =================
// block (8,32) = 256 threads -> 32x32 output tile, each thread 4 consecutive x pixels.
// Dyn smem (floats):
//   sF   [16][34][36]   feat tile, current ic group      19584
//   sW2g [16ic][9tap][32oc]                               4608
//   sX   [36][37]       input tile (halo 2)               1332
//   sW1t [9tap][32oc]                                      288
//   sW3  [32]                                               32
#define CF_SF   0
#define CF_SW2  19584
#define CF_SX   24192
#define CF_SW1  25524
#define CF_SW3  25812
#define CF_TOTAL (25844*4)

__global__ __launch_bounds__(256, 1) void k_conv123(const float* __restrict__ x,
                                                    const float* __restrict__ w1,
                                                    const float* __restrict__ w2,
                                                    const float* __restrict__ w3){
    extern __shared__ float sm[];
    float* sF  = sm + CF_SF;
    float* sW2 = sm + CF_SW2;
    float* sX  = sm + CF_SX;
    float* sW1 = sm + CF_SW1;
    float* sW3 = sm + CF_SW3;

    int tx = threadIdx.x;           // 0..7
    int ty = threadIdx.y;           // 0..31
    int tid = ty*8 + tx;

    for (int i = tid; i < 288; i += 256){
        int tap = i >> 5, oc = i & 31;
        sW1[i] = w1[oc*9 + tap];                      // [tap][oc]
    }
    if (tid < 32) sW3[tid] = w3[tid];

    int bx0 = blockIdx.x*32, by0 = blockIdx.y*32;

    // input tile 36x36, origin (by0-2, bx0-2), stride 37
    for (int i = tid; i < 36*36; i += 256){
        int yy = i/36, xxv = i%36;
        int gy = by0-2+yy, gx = bx0-2+xxv;
        float v = 0.f;
        if ((unsigned)gy < 2048u && (unsigned)gx < 2048u) v = x[(gy<<11)+gx];
        sX[yy*37 + xxv] = v;
    }
    __syncthreads();

    unsigned long long acc0[16], acc1[16], acc2[16], acc3[16];
    #pragma unroll
    for (int q = 0; q < 16; q++){ acc0[q]=0ull; acc1[q]=0ull; acc2[q]=0ull; acc3[q]=0ull; }

    for (int g = 0; g < 2; g++){
        if (g) __syncthreads();
        // weights for this ic group: [icl][tap][oc]
        for (int i = tid; i < 4608; i += 256){
            int icl = i/288, r = i%288, tap = r/32, oc = r%32;
            sW2[(icl*9+tap)*32 + oc] = w2[((size_t)oc*32 + (g*16+icl))*9 + tap];
        }
        // conv1 for this oc group (oc = g*16 .. g*16+15) over 34x34 feat region
        for (int i = tid; i < 34*34; i += 256){
            int fy = i/34, fx = i%34;
            const float* base = sX + fy*37 + fx;
            unsigned long long vp[9];
            #pragma unroll
            for (int r = 0; r < 3; r++)
                #pragma unroll
                for (int c = 0; c < 3; c++) vp[r*3+c] = pack2(base[r*37+c]);
            float* outp = sF + fy*36 + fx;
            #pragma unroll
            for (int q = 0; q < 8; q++){
                unsigned long long a = 0ull;
                #pragma unroll
                for (int t = 0; t < 9; t++){
                    unsigned long long w = ((const unsigned long long*)(sW1 + t*32))[g*8 + q];
                    fma2(a, vp[t], w);
                }
                float2 f = unpack2(a);
                outp[(2*q  )*1224] = fmaxf(f.x, 0.f);
                outp[(2*q+1)*1224] = fmaxf(f.y, 0.f);
            }
        }
        __syncthreads();

        // conv2: each thread 4 consecutive x pixels, 32 oc (16 f32x2)
        const float* bp0 = sF + ty*36 + 4*tx;
        for (int icl = 0; icl < 16; icl++){
            const float* bp = bp0 + icl*1224;
            #pragma unroll
            for (int r = 0; r < 3; r++){
                const float* rp = bp + r*36;
                float4 A = *(const float4*)(rp);
                float4 B = *(const float4*)(rp + 4);
                unsigned long long pk[6];
                pk[0] = pack2(A.x); pk[1] = pack2(A.y); pk[2] = pack2(A.z);
                pk[3] = pack2(A.w); pk[4] = pack2(B.x); pk[5] = pack2(B.y);
                const unsigned long long* wr = (const unsigned long long*)(sW2 + (icl*9 + r*3)*32);
                #pragma unroll
                for (int c = 0; c < 3; c++){
                    const unsigned long long* w = wr + c*16;
                    #pragma unroll
                    for (int q = 0; q < 16; q++){
                        unsigned long long wq = w[q];
                        fma2(acc0[q], pk[c+0], wq);
                        fma2(acc1[q], pk[c+1], wq);
                        fma2(acc2[q], pk[c+2], wq);
                        fma2(acc3[q], pk[c+3], wq);
                    }
                }
            }
        }
    }

    // relu + 1x1 conv + threshold; order oc 0..31 (same as reference-exact R2/R3)
    float z0 = 0.f, z1 = 0.f, z2 = 0.f, z3 = 0.f;
    #pragma unroll
    for (int q = 0; q < 16; q++){
        float wlo = sW3[2*q], whi = sW3[2*q+1];
        float2 f;
        f = unpack2(acc0[q]); z0 += fmaxf(f.x,0.f)*wlo; z0 += fmaxf(f.y,0.f)*whi;
        f = unpack2(acc1[q]); z1 += fmaxf(f.x,0.f)*wlo; z1 += fmaxf(f.y,0.f)*whi;
        f = unpack2(acc2[q]); z2 += fmaxf(f.x,0.f)*wlo; z2 += fmaxf(f.y,0.f)*whi;
        f = unpack2(acc3[q]); z3 += fmaxf(f.x,0.f)*wlo; z3 += fmaxf(f.y,0.f)*whi;
    }
    int y = by0 + ty, xg = bx0 + 4*tx;
    int p = (y<<11) + xg;
    int4 lab;
    lab.x = (z0 > 0.f) ? (p  ) : BIGL;
    lab.y = (z1 > 0.f) ? (p+1) : BIGL;
    lab.z = (z2 > 0.f) ? (p+2) : BIGL;
    lab.w = (z3 > 0.f) ? (p+3) : BIGL;
    *(int4*)(g_labA + p) = lab;
}

// ================= connected components: 8 exact Jacobi steps, int4, sentinel ring =================
// interior 64x64, region 80x80 valid at rows 1..80, cols 4..83 of an 82x88 tile; ring = BIGL.
#define CC_STRIDE 88
#define CC_CELLS  (82*CC_STRIDE)     // 7216
#define CC_SMEM   (2*CC_CELLS*4)     // 57728 B

__device__ __forceinline__ void cc_step(const int* __restrict__ cur, int* __restrict__ nxt, int off){
    int4 c = *(const int4*)(cur + off);
    int4 u = *(const int4*)(cur + off - CC_STRIDE);
    int4 d = *(const int4*)(cur + off + CC_STRIDE);
    int l = cur[off-1], r = cur[off+4];
    int4 o; int m;
    m = min(min(u.x,d.x), min(l,   c.y)); o.x = (c.x==BIGL) ? BIGL : min(c.x, m);
    m = min(min(u.y,d.y), min(c.x, c.z)); o.y = (c.y==BIGL) ? BIGL : min(c.y, m);
    m = min(min(u.z,d.z), min(c.y, c.w)); o.z = (c.z==BIGL) ? BIGL : min(c.z, m);
    m = min(min(u.w,d.w), min(c.z, r  )); o.w = (c.w==BIGL) ? BIGL : min(c.w, m);
    *(int4*)(nxt + off) = o;
}

__global__ __launch_bounds__(1024) void k_cc(const int* __restrict__ src, int* __restrict__ dst){
    extern __shared__ int sh[];
    int* A = sh;
    int* B = sh + CC_CELLS;
    int tid = threadIdx.x;
    int gx0 = blockIdx.x*64 - 8, gy0 = blockIdx.y*64 - 8;

    // fill both buffers with BIGL (sentinels persist; valid cells overwritten)
    for (int s = tid; s < CC_CELLS; s += 1024){ A[s] = BIGL; B[s] = BIGL; }
    __syncthreads();

    // load 80x80 valid region into A (int4 fast path)
    for (int v = tid; v < 1600; v += 1024){
        int vy = v/20, vx = (v%20)*4;
        int gy = gy0 + vy, gxb = gx0 + vx;
        int off = (1+vy)*CC_STRIDE + 4 + vx;
        if ((unsigned)gy < 2048u && gxb >= 0 && gxb + 3 < 2048){
            *(int4*)(A + off) = *(const int4*)(src + (gy<<11) + gxb);
        } else if ((unsigned)gy < 2048u){
            #pragma unroll
            for (int k = 0; k < 4; k++){
                int gx = gxb + k;
                A[off+k] = ((unsigned)gx < 2048u) ? src[(gy<<11)+gx] : BIGL;
            }
        }
    }
    __syncthreads();

    // precompute this thread's cell offsets
    int j0 = tid;
    int off0 = (1 + j0/20)*CC_STRIDE + 4 + (j0%20)*4;
    int j1 = tid + 1024;
    int off1 = (1 + j1/20)*CC_STRIDE + 4 + (j1%20)*4;
    bool has1 = (j1 < 1600);

    int* cur = A; int* nxt = B;
    #pragma unroll
    for (int s = 0; s < 8; s++){
        cc_step(cur, nxt, off0);
        if (has1) cc_step(cur, nxt, off1);
        __syncthreads();
        int* t = cur; cur = nxt; nxt = t;
    }

    // write interior 64x64 (starts at valid cell (8,8) -> smem (9,12))
    int row = tid >> 4, c16 = tid & 15;
    int soff = (9 + row)*CC_STRIDE + 12 + c16*4;
    int gy = blockIdx.y*64 + row, gx = blockIdx.x*64 + c16*4;
    *(int4*)(dst + (gy<<11) + gx) = *(const int4*)(cur + soff);
}

// ---------------- histogram ----------------
__global__ void k_zero_counts(){
    int i = blockIdx.x*1024 + threadIdx.x;
    if (i < NLBL) g_counts[i] = 0;
}
__global__ void k_count(){
    int p = blockIdx.x*256 + threadIdx.x;
    int l = g_labA[p];
    unsigned mk = __match_any_sync(0xffffffffu, l);
    int leader = __ffs(mk) - 1;
    if ((threadIdx.x & 31) == leader && l != BIGL)
        atomicAdd(&g_counts[l], __popc(mk));
}

// ---------------- exact top-16 (count desc, label asc): two-stage ----------------
__global__ void k_topA(){
    __shared__ unsigned long long s[256*16];
    int chunk = (NLBL + NBLK_TOP - 1)/NBLK_TOP;
    int lo = blockIdx.x*chunk;
    int hi = min(NLBL, lo + chunk);
    unsigned long long best[16];
    #pragma unroll
    for (int i = 0; i < 16; i++) best[i] = 0ull;
    unsigned long long bmin = 0ull; int bpos = 0;
    for (int i = lo + threadIdx.x; i < hi; i += 256){
        unsigned long long key = ((unsigned long long)(unsigned)g_counts[i] << 32)
                               | (unsigned)(~(unsigned)i);
        if (key > bmin){
            best[bpos] = key;
            bmin = best[0]; bpos = 0;
            #pragma unroll
            for (int j = 1; j < 16; j++) if (best[j] < bmin){ bmin = best[j]; bpos = j; }
        }
    }
    for (int j = 0; j < 16; j++) s[threadIdx.x*16 + j] = best[j];
    __syncthreads();
    if (threadIdx.x < 32){
        for (int r = 0; r < 16; r++){
            unsigned long long m = 0ull; int mp = -1;
            for (int i = threadIdx.x; i < 4096; i += 32){
                unsigned long long v = s[i];
                if (v > m){ m = v; mp = i; }
            }
            for (int off = 16; off; off >>= 1){
                unsigned long long om = __shfl_down_sync(0xffffffffu, m, off);
                int op = __shfl_down_sync(0xffffffffu, mp, off);
                if (om > m){ m = om; mp = op; }
            }
            m  = __shfl_sync(0xffffffffu, m, 0);
            mp = __shfl_sync(0xffffffffu, mp, 0);
            if (threadIdx.x == 0){
                g_cand[blockIdx.x*16 + r] = m;
                if (mp >= 0) s[mp] = 0ull;
            }
            __syncwarp();
        }
    }
}
__global__ void k_topB(){
    __shared__ unsigned long long s[2048];
    int tid = threadIdx.x;
    for (int i = tid; i < 2048; i += 256) s[i] = (i < NBLK_TOP*16) ? g_cand[i] : 0ull;
    __syncthreads();
    if (tid < 32){
        for (int r = 0; r < 16; r++){
            unsigned long long m = 0ull; int mp = -1;
            for (int i = tid; i < 2048; i += 32){
                unsigned long long v = s[i];
                if (v > m){ m = v; mp = i; }
            }
            for (int off = 16; off; off >>= 1){
                unsigned long long om = __shfl_down_sync(0xffffffffu, m, off);
                int op = __shfl_down_sync(0xffffffffu, mp, off);
                if (om > m){ m = om; mp = op; }
            }
            m  = __shfl_sync(0xffffffffu, m, 0);
            mp = __shfl_sync(0xffffffffu, mp, 0);
            if (tid == 0){
                g_cnts[r] = (int)(m >> 32);
                g_lids[r] = (int)(~(unsigned)(m & 0xffffffffull));
                if (mp >= 0) s[mp] = 0ull;
            }
            __syncwarp();
        }
    }
}

// ---------------- bounding boxes ----------------
__global__ void k_bbinit(){
    int k = threadIdx.x;
    if (k < 16){ g_bbox[k][0] = 0x7FFFFFFF; g_bbox[k][1] = -1; g_bbox[k][2] = 0x7FFFFFFF; g_bbox[k][3] = -1; }
}
__global__ void k_bbox(){
    __shared__ int slid[16];
    __shared__ int sbb[16][4];
    int tid = threadIdx.x;
    if (tid < 16){
        slid[tid] = g_lids[tid];
        sbb[tid][0] = 0x7FFFFFFF; sbb[tid][1] = -1; sbb[tid][2] = 0x7FFFFFFF; sbb[tid][3] = -1;
    }
    __syncthreads();
    int base = blockIdx.x*1024;
    for (int q = 0; q < 4; q++){
        int p = base + q*256 + tid;
        int l = g_labA[p];
        if (l != BIGL){
            int y = p >> 11, x = p & 2047;
            #pragma unroll
            for (int k = 0; k < 16; k++) if (l == slid[k]){
                if (y < sbb[k][0]) atomicMin(&sbb[k][0], y);
                if (y > sbb[k][1]) atomicMax(&sbb[k][1], y);
                if (x < sbb[k][2]) atomicMin(&sbb[k][2], x);
                if (x > sbb[k][3]) atomicMax(&sbb[k][3], x);
            }
        }
    }
    __syncthreads();
    if (tid < 16 && sbb[tid][0] != 0x7FFFFFFF){
        atomicMin(&g_bbox[tid][0], sbb[tid][0]);
        atomicMax(&g_bbox[tid][1], sbb[tid][1]);
        atomicMin(&g_bbox[tid][2], sbb[tid][2]);
        atomicMax(&g_bbox[tid][3], sbb[tid][3]);
    }
}

// ---------------- ROI bilinear resize (227x227) ----------------
__global__ void k_roi(const float* __restrict__ img){
    int k = blockIdx.x;
    int y0 = g_bbox[k][0], y1 = g_bbox[k][1], x0 = g_bbox[k][2], x1 = g_bbox[k][3];
    if (y0 == 0x7FFFFFFF){ y0 = 0; y1 = 2047; x0 = 0; x1 = 2047; }  // empty comp: argmax(all-false)=0
    float dy = (float)(y1 - y0), dx = (float)(x1 - x0);
    for (int idx = threadIdx.x; idx < 227*227; idx += blockDim.x){
        int i = idx/227, j = idx%227;
        float gy = (float)y0 + ((float)i/226.0f)*dy;
        float gx = (float)x0 + ((float)j/226.0f)*dx;
        int yf = min(max((int)floorf(gy), 0), 2046);
        int xf = min(max((int)floorf(gx), 0), 2046);
        float fy = gy - (float)yf, fx = gx - (float)xf;
        const float* r0 = img + (yf<<11) + xf;
        float v00 = r0[0], v01 = r0[1], v10 = r0[2048], v11 = r0[2049];
        g_roi[k*51529 + idx] = (1.f-fy)*((1.f-fx)*v00 + fx*v01) + fy*((1.f-fx)*v10 + fx*v11);
    }
}

// ---------------- classifier conv1: 7x7 s4 VALID, 1->16, relu ----------------
__global__ void k_c1(const float* __restrict__ cw1){
    __shared__ float sw[784];
    int tid = threadIdx.x;
    for (int i = tid; i < 784; i += 256) sw[i] = cw1[i];
    __syncthreads();
    int o = blockIdx.x*256 + tid;           // 16*16*56*56 = 802816 total
    int k = o/50176, r = o%50176, oc = r/3136, s = r%3136, oy = s/56, ox = s%56;
    const float* roi = g_roi + k*51529;
    const float* wb = sw + oc*49;
    float a = 0.f;
    #pragma unroll
    for (int ky = 0; ky < 7; ky++){
        const float* rr = roi + (oy*4+ky)*227 + ox*4;
        #pragma unroll
        for (int kx = 0; kx < 7; kx++) a += rr[kx]*wb[ky*7+kx];
    }
    g_h1[o] = fmaxf(a, 0.f);
}

// ---------------- classifier conv2: 3x3 s2 VALID, 16->32, relu ----------------
__global__ void k_c2(const float* __restrict__ cw2){
    __shared__ float sw[4608];
    int tid = threadIdx.x;
    for (int i = tid; i < 4608; i += 256) sw[i] = cw2[i];
    __syncthreads();
    int o = blockIdx.x*256 + tid;           // 16*32*27*27 = 373248
    int k = o/23328, r = o%23328, oc = r/729, s = r%729, oy = s/27, ox = s%27;
    const float* h = g_h1 + (size_t)k*16*3136;
    float a = 0.f;
    for (int ic = 0; ic < 16; ic++){
        const float* hb = h + ic*3136 + (oy*2)*56 + ox*2;
        const float* wb = sw + (oc*16+ic)*9;
        #pragma unroll
        for (int ky = 0; ky < 3; ky++)
            #pragma unroll
            for (int kx = 0; kx < 3; kx++)
                a += hb[ky*56+kx]*wb[ky*3+kx];
    }
    g_h2[o] = fmaxf(a, 0.f);
}

// ---------------- global mean + fc + argmax ----------------
__global__ void k_cls(const float* __restrict__ fc){
    __shared__ float ssum[32];
    int k = blockIdx.x;
    int tid = threadIdx.x, w = tid >> 5, lane = tid & 31;
    for (int oc = w*4; oc < w*4+4; oc++){
        float s = 0.f;
        const float* h = g_h2 + ((size_t)(k*32+oc))*729;
        for (int i = lane; i < 729; i += 32) s += h[i];
        for (int off = 16; off; off >>= 1) s += __shfl_down_sync(0xffffffffu, s, off);
        if (lane == 0) ssum[oc] = s;
    }
    __syncthreads();
    if (tid == 0){
        float best = -1e30f; int bc = 0;
        for (int c = 0; c < 4; c++){
            float lg = 0.f;
            for (int oc = 0; oc < 32; oc++) lg += (ssum[oc]*(1.0f/729.0f))*fc[oc*4+c];
            if (lg > best){ best = lg; bc = c; }
        }
        g_cls[k] = bc;
    }
}

// ---------------- final mask composition ----------------
__global__ void k_final(float* __restrict__ out){
    __shared__ int slid[16], scnt[16], scls[16];
    int tid = threadIdx.x;
    if (tid < 16){ slid[tid] = g_lids[tid]; scnt[tid] = g_cnts[tid]; scls[tid] = g_cls[tid]; }
    __syncthreads();
    int p = blockIdx.x*256 + tid;
    int l = g_labA[p];
    float o0 = 0.f, o1 = 0.f, o2 = 0.f, o3 = 0.f;
    #pragma unroll
    for (int k = 0; k < 16; k++){
        if (scnt[k] >= MINSZ && slid[k] == l){
            int c = scls[k];
            if (c == 0) o0 = 1.f; else if (c == 1) o1 = 1.f; else if (c == 2) o2 = 1.f; else o3 = 1.f;
        }
    }
    out[p] = o0;
    out[NPIX + p] = o1;
    out[2*NPIX + p] = o2;
    out[3*NPIX + p] = o3;
}

// ---------------- launch ----------------
extern "C" void kernel_launch(void* const* d_in, const int* in_sizes, int n_in,
                              void* d_out, int out_size){
    const float *x = nullptr, *w1 = nullptr, *w2 = nullptr, *w3 = nullptr;
    const float *cw1 = nullptr, *cw2 = nullptr, *fc = nullptr;
    for (int i = 0; i < n_in; i++){
        switch (in_sizes[i]){
            case 4194304: x   = (const float*)d_in[i]; break;
            case 288:     w1  = (const float*)d_in[i]; break;
            case 9216:    w2  = (const float*)d_in[i]; break;
            case 32:      w3  = (const float*)d_in[i]; break;
            case 784:     cw1 = (const float*)d_in[i]; break;
            case 4608:    cw2 = (const float*)d_in[i]; break;
            case 128:     fc  = (const float*)d_in[i]; break;
            default: break;
        }
    }
    float* out = (float*)d_out;

    cudaFuncSetAttribute(k_conv123, cudaFuncAttributeMaxDynamicSharedMemorySize, CF_TOTAL);
    cudaFuncSetAttribute(k_cc, cudaFuncAttributeMaxDynamicSharedMemorySize, CC_SMEM);

    k_conv123<<<dim3(64,64), dim3(8,32), CF_TOTAL>>>(x, w1, w2, w3);

    int* la = nullptr; int* lb = nullptr;
    cudaGetSymbolAddress((void**)&la, g_labA);
    cudaGetSymbolAddress((void**)&lb, g_labB);
    for (int i = 0; i < 4; i++){
        k_cc<<<dim3(32,32), 1024, CC_SMEM>>>(la, lb);   // A -> B
        k_cc<<<dim3(32,32), 1024, CC_SMEM>>>(lb, la);   // B -> A
    }

    k_zero_counts<<<(NLBL+1023)/1024, 1024>>>();
    k_count<<<NPIX/256, 256>>>();
    k_topA<<<NBLK_TOP, 256>>>();
    k_topB<<<1, 256>>>();

    k_bbinit<<<1, 16>>>();
    k_bbox<<<NPIX/1024, 256>>>();

    k_roi<<<16, 256>>>(x);
    k_c1<<<802816/256, 256>>>(cw1);
    k_c2<<<373248/256, 256>>>(cw2);
    k_cls<<<16, 256>>>(fc);

    k_final<<<NPIX/256, 256>>>(out);
}

// round 5
// speedup vs baseline: 2.0755x; 1.0014x over previous
#include <cuda_runtime.h>
#include <cstdint>

#define Hh 2048
#define Ww 2048
#define NPIX (Hh*Ww)            // 4194304
#define BIGL NPIX               // background label
#define NLBL (NPIX+1)
#define KTOP 16
#define NBLK_TOP 120
#define MINSZ 64

// ---------------- device scratch (no allocations allowed) ----------------
__device__ int   g_labA[NPIX];
__device__ int   g_labB[NPIX];
__device__ int   g_counts[NLBL];
__device__ unsigned long long g_cand[NBLK_TOP*KTOP];
__device__ int   g_lids[KTOP];
__device__ int   g_cnts[KTOP];
__device__ int   g_bbox[KTOP][4];              // y0,y1,x0,x1
__device__ int   g_cls[KTOP];
__device__ float g_roi[KTOP*227*227];
__device__ float g_h1[KTOP*16*56*56];
__device__ float g_h2[KTOP*32*27*27];

// ---------------- f32x2 helpers ----------------
__device__ __forceinline__ unsigned long long pack2(float v){
    unsigned long long r; asm("mov.b64 %0, {%1, %1};" : "=l"(r) : "f"(v)); return r;
}
__device__ __forceinline__ void fma2(unsigned long long& a, unsigned long long v, unsigned long long w){
    asm("fma.rn.f32x2 %0, %1, %2, %0;" : "+l"(a) : "l"(v), "l"(w));
}
__device__ __forceinline__ float2 unpack2(unsigned long long a){
    float2 f; asm("mov.b64 {%0, %1}, %2;" : "=f"(f.x), "=f"(f.y) : "l"(a)); return f;
}

// ================= fused conv1+conv2+conv3+threshold =================
// block (8,32) = 256 threads -> 32x32 output tile, 4 consecutive x px / thread.
// Two passes over oc (16 oc each) so accumulators = 32 u64 -> 2 blocks/SM.
// Per pass: 4 ic-groups of 8; conv1 recomputed per pass (cheap).
// Dyn smem (floats):
//   sF   [8][34][36]   feat tile, current ic group        9792
//   sW2  [8ic][9tap][16oc]                                1152
//   sX   [36][37]      input tile (halo 2)                1332
//   sW1  [9tap][32oc]                                      288
//   sW3  [32]                                               32
#define CF_SF   0
#define CF_SW2  9792
#define CF_SX   10944
#define CF_SW1  12276
#define CF_SW3  12564
#define CF_TOTAL (12596*4)
#define FSTR 1224   // 34*36

__global__ __launch_bounds__(256, 2) void k_conv123(const float* __restrict__ x,
                                                    const float* __restrict__ w1,
                                                    const float* __restrict__ w2,
                                                    const float* __restrict__ w3){
    extern __shared__ float sm[];
    float* sF  = sm + CF_SF;
    float* sW2 = sm + CF_SW2;
    float* sX  = sm + CF_SX;
    float* sW1 = sm + CF_SW1;
    float* sW3 = sm + CF_SW3;

    int tx = threadIdx.x;           // 0..7
    int ty = threadIdx.y;           // 0..31
    int tid = ty*8 + tx;

    for (int i = tid; i < 288; i += 256){
        int tap = i >> 5, oc = i & 31;
        sW1[i] = w1[oc*9 + tap];                      // [tap][oc]
    }
    if (tid < 32) sW3[tid] = w3[tid];

    int bx0 = blockIdx.x*32, by0 = blockIdx.y*32;

    // input tile 36x36, origin (by0-2, bx0-2), stride 37
    for (int i = tid; i < 36*36; i += 256){
        int yy = i/36, xxv = i%36;
        int gy = by0-2+yy, gx = bx0-2+xxv;
        float v = 0.f;
        if ((unsigned)gy < 2048u && (unsigned)gx < 2048u) v = x[(gy<<11)+gx];
        sX[yy*37 + xxv] = v;
    }

    float z0 = 0.f, z1 = 0.f, z2 = 0.f, z3 = 0.f;
    const unsigned long long* w1u = (const unsigned long long*)sW1;

    for (int p = 0; p < 2; p++){
        unsigned long long acc0[8], acc1[8], acc2[8], acc3[8];
        #pragma unroll
        for (int q = 0; q < 8; q++){ acc0[q]=0ull; acc1[q]=0ull; acc2[q]=0ull; acc3[q]=0ull; }

        for (int g = 0; g < 4; g++){
            __syncthreads();   // protect sF/sW2 readers of previous group (and sX writers on first)
            // weights for (pass p, group g): [icl][tap][16 oc]
            for (int i = tid; i < 1152; i += 256){
                int icl = i >> 7, r = i & 127, tap = r >> 4, ocl = r & 15;
                sW2[i] = w2[((size_t)(p*16+ocl)*32 + (g*8+icl))*9 + tap];
            }
            // conv1 for channels g*8 .. g*8+7 over 34x34 region
            for (int i = tid; i < 34*34; i += 256){
                int fy = i/34, fx = i - fy*34;
                const float* base = sX + fy*37 + fx;
                unsigned long long vp[9];
                #pragma unroll
                for (int r = 0; r < 3; r++)
                    #pragma unroll
                    for (int c = 0; c < 3; c++) vp[r*3+c] = pack2(base[r*37+c]);
                float* outp = sF + fy*36 + fx;
                #pragma unroll
                for (int q = 0; q < 4; q++){
                    unsigned long long a = 0ull;
                    #pragma unroll
                    for (int t = 0; t < 9; t++) fma2(a, vp[t], w1u[t*16 + g*4 + q]);
                    float2 f = unpack2(a);
                    outp[(2*q  )*FSTR] = fmaxf(f.x, 0.f);
                    outp[(2*q+1)*FSTR] = fmaxf(f.y, 0.f);
                }
            }
            __syncthreads();

            // conv2 accumulate: 4 px, 16 oc (8 u64), 8 ic
            const float* bp0 = sF + ty*36 + 4*tx;
            for (int icl = 0; icl < 8; icl++){
                const float* bp = bp0 + icl*FSTR;
                #pragma unroll
                for (int r = 0; r < 3; r++){
                    const float* rp = bp + r*36;
                    float4 A = *(const float4*)(rp);
                    float4 B = *(const float4*)(rp + 4);
                    unsigned long long pk[6];
                    pk[0] = pack2(A.x); pk[1] = pack2(A.y); pk[2] = pack2(A.z);
                    pk[3] = pack2(A.w); pk[4] = pack2(B.x); pk[5] = pack2(B.y);
                    const unsigned long long* wr = (const unsigned long long*)(sW2 + (icl*9 + r*3)*16);
                    #pragma unroll
                    for (int c = 0; c < 3; c++){
                        const unsigned long long* w = wr + c*8;
                        #pragma unroll
                        for (int q = 0; q < 8; q++){
                            unsigned long long wq = w[q];
                            fma2(acc0[q], pk[c+0], wq);
                            fma2(acc1[q], pk[c+1], wq);
                            fma2(acc2[q], pk[c+2], wq);
                            fma2(acc3[q], pk[c+3], wq);
                        }
                    }
                }
            }
        }
        // fold this oc-half into z in oc order (left-to-right fp32 sum preserved)
        #pragma unroll
        for (int q = 0; q < 8; q++){
            float wlo = sW3[p*16 + 2*q], whi = sW3[p*16 + 2*q + 1];
            float2 f;
            f = unpack2(acc0[q]); z0 += fmaxf(f.x,0.f)*wlo; z0 += fmaxf(f.y,0.f)*whi;
            f = unpack2(acc1[q]); z1 += fmaxf(f.x,0.f)*wlo; z1 += fmaxf(f.y,0.f)*whi;
            f = unpack2(acc2[q]); z2 += fmaxf(f.x,0.f)*wlo; z2 += fmaxf(f.y,0.f)*whi;
            f = unpack2(acc3[q]); z3 += fmaxf(f.x,0.f)*wlo; z3 += fmaxf(f.y,0.f)*whi;
        }
    }

    int y = by0 + ty, xg = bx0 + 4*tx;
    int ppix = (y<<11) + xg;
    int4 lab;
    lab.x = (z0 > 0.f) ? (ppix  ) : BIGL;
    lab.y = (z1 > 0.f) ? (ppix+1) : BIGL;
    lab.z = (z2 > 0.f) ? (ppix+2) : BIGL;
    lab.w = (z3 > 0.f) ? (ppix+3) : BIGL;
    *(int4*)(g_labA + ppix) = lab;
}

// ================= connected components: 8 exact Jacobi steps, int4, sentinel ring =================
// interior 64x64, region 80x80 valid at rows 1..80, cols 4..83 of an 82x88 tile; ring = BIGL.
// Step k only computes cells in [k, 79-k]^2 (region coords) — anything outside is dead.
#define CC_STRIDE 88
#define CC_CELLS  (82*CC_STRIDE)     // 7216
#define CC_SMEM   (2*CC_CELLS*4)     // 57728 B

__device__ __forceinline__ void cc_step(const int* __restrict__ cur, int* __restrict__ nxt, int off){
    int4 c = *(const int4*)(cur + off);
    int4 u = *(const int4*)(cur + off - CC_STRIDE);
    int4 d = *(const int4*)(cur + off + CC_STRIDE);
    int l = cur[off-1], r = cur[off+4];
    int4 o; int m;
    m = min(min(u.x,d.x), min(l,   c.y)); o.x = (c.x==BIGL) ? BIGL : min(c.x, m);
    m = min(min(u.y,d.y), min(c.x, c.z)); o.y = (c.y==BIGL) ? BIGL : min(c.y, m);
    m = min(min(u.z,d.z), min(c.y, c.w)); o.z = (c.z==BIGL) ? BIGL : min(c.z, m);
    m = min(min(u.w,d.w), min(c.z, r  )); o.w = (c.w==BIGL) ? BIGL : min(c.w, m);
    *(int4*)(nxt + off) = o;
}

__global__ __launch_bounds__(1024) void k_cc(const int* __restrict__ src, int* __restrict__ dst){
    extern __shared__ int sh[];
    int* A = sh;
    int* B = sh + CC_CELLS;
    int tid = threadIdx.x;
    int gx0 = blockIdx.x*64 - 8, gy0 = blockIdx.y*64 - 8;

    // fill both buffers with BIGL (sentinels persist; valid cells overwritten)
    for (int s = tid; s < CC_CELLS; s += 1024){ A[s] = BIGL; B[s] = BIGL; }
    __syncthreads();

    // load 80x80 valid region into A (int4 fast path)
    for (int v = tid; v < 1600; v += 1024){
        int vy = v/20, vx = (v%20)*4;
        int gy = gy0 + vy, gxb = gx0 + vx;
        int off = (1+vy)*CC_STRIDE + 4 + vx;
        if ((unsigned)gy < 2048u && gxb >= 0 && gxb + 3 < 2048){
            *(int4*)(A + off) = *(const int4*)(src + (gy<<11) + gxb);
        } else if ((unsigned)gy < 2048u){
            #pragma unroll
            for (int k = 0; k < 4; k++){
                int gx = gxb + k;
                A[off+k] = ((unsigned)gx < 2048u) ? src[(gy<<11)+gx] : BIGL;
            }
        }
    }
    __syncthreads();

    // this thread's two cells (region coords)
    int j0 = tid;
    int vy0 = j0/20, cx0 = (j0 - vy0*20)*4;
    int off0 = (1 + vy0)*CC_STRIDE + 4 + cx0;
    int j1 = tid + 1024;
    int vy1 = j1/20, cx1 = (j1 - vy1*20)*4;
    int off1 = (1 + vy1)*CC_STRIDE + 4 + cx1;
    bool has1 = (j1 < 1600);

    int* cur = A; int* nxt = B;
    #pragma unroll
    for (int s = 1; s <= 8; s++){
        if (vy0 >= s && vy0 <= 79-s && cx0+3 >= s && cx0 <= 79-s) cc_step(cur, nxt, off0);
        if (has1 && vy1 >= s && vy1 <= 79-s && cx1+3 >= s && cx1 <= 79-s) cc_step(cur, nxt, off1);
        __syncthreads();
        int* t = cur; cur = nxt; nxt = t;
    }

    // write interior 64x64 (region cell (8,8) -> smem (9,12))
    int row = tid >> 4, c16 = tid & 15;
    int soff = (9 + row)*CC_STRIDE + 12 + c16*4;
    int gy = blockIdx.y*64 + row, gx = blockIdx.x*64 + c16*4;
    *(int4*)(dst + (gy<<11) + gx) = *(const int4*)(cur + soff);
}

// ---------------- histogram ----------------
__global__ void k_zero_counts(){
    int i = blockIdx.x*1024 + threadIdx.x;
    if (i < NLBL) g_counts[i] = 0;
}
__global__ void k_count(){
    int p = blockIdx.x*256 + threadIdx.x;
    int l = g_labA[p];
    unsigned mk = __match_any_sync(0xffffffffu, l);
    int leader = __ffs(mk) - 1;
    if ((threadIdx.x & 31) == leader && l != BIGL)
        atomicAdd(&g_counts[l], __popc(mk));
}

// ---------------- exact top-16 (count desc, label asc): two-stage ----------------
__global__ void k_topA(){
    __shared__ unsigned long long s[256*16];
    int chunk = (NLBL + NBLK_TOP - 1)/NBLK_TOP;
    int lo = blockIdx.x*chunk;
    int hi = min(NLBL, lo + chunk);
    unsigned long long best[16];
    #pragma unroll
    for (int i = 0; i < 16; i++) best[i] = 0ull;
    unsigned long long bmin = 0ull; int bpos = 0;
    for (int i = lo + threadIdx.x; i < hi; i += 256){
        unsigned long long key = ((unsigned long long)(unsigned)g_counts[i] << 32)
                               | (unsigned)(~(unsigned)i);
        if (key > bmin){
            best[bpos] = key;
            bmin = best[0]; bpos = 0;
            #pragma unroll
            for (int j = 1; j < 16; j++) if (best[j] < bmin){ bmin = best[j]; bpos = j; }
        }
    }
    for (int j = 0; j < 16; j++) s[threadIdx.x*16 + j] = best[j];
    __syncthreads();
    if (threadIdx.x < 32){
        for (int r = 0; r < 16; r++){
            unsigned long long m = 0ull; int mp = -1;
            for (int i = threadIdx.x; i < 4096; i += 32){
                unsigned long long v = s[i];
                if (v > m){ m = v; mp = i; }
            }
            for (int off = 16; off; off >>= 1){
                unsigned long long om = __shfl_down_sync(0xffffffffu, m, off);
                int op = __shfl_down_sync(0xffffffffu, mp, off);
                if (om > m){ m = om; mp = op; }
            }
            m  = __shfl_sync(0xffffffffu, m, 0);
            mp = __shfl_sync(0xffffffffu, mp, 0);
            if (threadIdx.x == 0){
                g_cand[blockIdx.x*16 + r] = m;
                if (mp >= 0) s[mp] = 0ull;
            }
            __syncwarp();
        }
    }
}
__global__ void k_topB(){
    __shared__ unsigned long long s[2048];
    int tid = threadIdx.x;
    for (int i = tid; i < 2048; i += 256) s[i] = (i < NBLK_TOP*16) ? g_cand[i] : 0ull;
    __syncthreads();
    if (tid < 32){
        for (int r = 0; r < 16; r++){
            unsigned long long m = 0ull; int mp = -1;
            for (int i = tid; i < 2048; i += 32){
                unsigned long long v = s[i];
                if (v > m){ m = v; mp = i; }
            }
            for (int off = 16; off; off >>= 1){
                unsigned long long om = __shfl_down_sync(0xffffffffu, m, off);
                int op = __shfl_down_sync(0xffffffffu, mp, off);
                if (om > m){ m = om; mp = op; }
            }
            m  = __shfl_sync(0xffffffffu, m, 0);
            mp = __shfl_sync(0xffffffffu, mp, 0);
            if (tid == 0){
                g_cnts[r] = (int)(m >> 32);
                g_lids[r] = (int)(~(unsigned)(m & 0xffffffffull));
                if (mp >= 0) s[mp] = 0ull;
            }
            __syncwarp();
        }
    }
}

// ---------------- bounding boxes ----------------
__global__ void k_bbinit(){
    int k = threadIdx.x;
    if (k < 16){ g_bbox[k][0] = 0x7FFFFFFF; g_bbox[k][1] = -1; g_bbox[k][2] = 0x7FFFFFFF; g_bbox[k][3] = -1; }
}
__global__ void k_bbox(){
    __shared__ int slid[16];
    __shared__ int sbb[16][4];
    int tid = threadIdx.x;
    if (tid < 16){
        slid[tid] = g_lids[tid];
        sbb[tid][0] = 0x7FFFFFFF; sbb[tid][1] = -1; sbb[tid][2] = 0x7FFFFFFF; sbb[tid][3] = -1;
    }
    __syncthreads();
    int base = blockIdx.x*1024;
    for (int q = 0; q < 4; q++){
        int p = base + q*256 + tid;
        int l = g_labA[p];
        if (l != BIGL){
            int y = p >> 11, x = p & 2047;
            #pragma unroll
            for (int k = 0; k < 16; k++) if (l == slid[k]){
                if (y < sbb[k][0]) atomicMin(&sbb[k][0], y);
                if (y > sbb[k][1]) atomicMax(&sbb[k][1], y);
                if (x < sbb[k][2]) atomicMin(&sbb[k][2], x);
                if (x > sbb[k][3]) atomicMax(&sbb[k][3], x);
            }
        }
    }
    __syncthreads();
    if (tid < 16 && sbb[tid][0] != 0x7FFFFFFF){
        atomicMin(&g_bbox[tid][0], sbb[tid][0]);
        atomicMax(&g_bbox[tid][1], sbb[tid][1]);
        atomicMin(&g_bbox[tid][2], sbb[tid][2]);
        atomicMax(&g_bbox[tid][3], sbb[tid][3]);
    }
}

// ---------------- ROI bilinear resize (227x227) ----------------
__global__ void k_roi(const float* __restrict__ img){
    int k = blockIdx.x;
    int y0 = g_bbox[k][0], y1 = g_bbox[k][1], x0 = g_bbox[k][2], x1 = g_bbox[k][3];
    if (y0 == 0x7FFFFFFF){ y0 = 0; y1 = 2047; x0 = 0; x1 = 2047; }  // empty comp: argmax(all-false)=0
    float dy = (float)(y1 - y0), dx = (float)(x1 - x0);
    for (int idx = threadIdx.x; idx < 227*227; idx += blockDim.x){
        int i = idx/227, j = idx%227;
        float gy = (float)y0 + ((float)i/226.0f)*dy;
        float gx = (float)x0 + ((float)j/226.0f)*dx;
        int yf = min(max((int)floorf(gy), 0), 2046);
        int xf = min(max((int)floorf(gx), 0), 2046);
        float fy = gy - (float)yf, fx = gx - (float)xf;
        const float* r0 = img + (yf<<11) + xf;
        float v00 = r0[0], v01 = r0[1], v10 = r0[2048], v11 = r0[2049];
        g_roi[k*51529 + idx] = (1.f-fy)*((1.f-fx)*v00 + fx*v01) + fy*((1.f-fx)*v10 + fx*v11);
    }
}

// ---------------- classifier conv1: 7x7 s4 VALID, 1->16, relu ----------------
__global__ void k_c1(const float* __restrict__ cw1){
    __shared__ float sw[784];
    int tid = threadIdx.x;
    for (int i = tid; i < 784; i += 256) sw[i] = cw1[i];
    __syncthreads();
    int o = blockIdx.x*256 + tid;           // 16*16*56*56 = 802816 total
    int k = o/50176, r = o%50176, oc = r/3136, s = r%3136, oy = s/56, ox = s%56;
    const float* roi = g_roi + k*51529;
    const float* wb = sw + oc*49;
    float a = 0.f;
    #pragma unroll
    for (int ky = 0; ky < 7; ky++){
        const float* rr = roi + (oy*4+ky)*227 + ox*4;
        #pragma unroll
        for (int kx = 0; kx < 7; kx++) a += rr[kx]*wb[ky*7+kx];
    }
    g_h1[o] = fmaxf(a, 0.f);
}

// ---------------- classifier conv2: 3x3 s2 VALID, 16->32, relu ----------------
__global__ void k_c2(const float* __restrict__ cw2){
    __shared__ float sw[4608];
    int tid = threadIdx.x;
    for (int i = tid; i < 4608; i += 256) sw[i] = cw2[i];
    __syncthreads();
    int o = blockIdx.x*256 + tid;           // 16*32*27*27 = 373248
    int k = o/23328, r = o%23328, oc = r/729, s = r%729, oy = s/27, ox = s%27;
    const float* h = g_h1 + (size_t)k*16*3136;
    float a = 0.f;
    for (int ic = 0; ic < 16; ic++){
        const float* hb = h + ic*3136 + (oy*2)*56 + ox*2;
        const float* wb = sw + (oc*16+ic)*9;
        #pragma unroll
        for (int ky = 0; ky < 3; ky++)
            #pragma unroll
            for (int kx = 0; kx < 3; kx++)
                a += hb[ky*56+kx]*wb[ky*3+kx];
    }
    g_h2[o] = fmaxf(a, 0.f);
}

// ---------------- global mean + fc + argmax ----------------
__global__ void k_cls(const float* __restrict__ fc){
    __shared__ float ssum[32];
    int k = blockIdx.x;
    int tid = threadIdx.x, w = tid >> 5, lane = tid & 31;
    for (int oc = w*4; oc < w*4+4; oc++){
        float s = 0.f;
        const float* h = g_h2 + ((size_t)(k*32+oc))*729;
        for (int i = lane; i < 729; i += 32) s += h[i];
        for (int off = 16; off; off >>= 1) s += __shfl_down_sync(0xffffffffu, s, off);
        if (lane == 0) ssum[oc] = s;
    }
    __syncthreads();
    if (tid == 0){
        float best = -1e30f; int bc = 0;
        for (int c = 0; c < 4; c++){
            float lg = 0.f;
            for (int oc = 0; oc < 32; oc++) lg += (ssum[oc]*(1.0f/729.0f))*fc[oc*4+c];
            if (lg > best){ best = lg; bc = c; }
        }
        g_cls[k] = bc;
    }
}

// ---------------- final mask composition ----------------
__global__ void k_final(float* __restrict__ out){
    __shared__ int slid[16], scnt[16], scls[16];
    int tid = threadIdx.x;
    if (tid < 16){ slid[tid] = g_lids[tid]; scnt[tid] = g_cnts[tid]; scls[tid] = g_cls[tid]; }
    __syncthreads();
    int p = blockIdx.x*256 + tid;
    int l = g_labA[p];
    float o0 = 0.f, o1 = 0.f, o2 = 0.f, o3 = 0.f;
    #pragma unroll
    for (int k = 0; k < 16; k++){
        if (scnt[k] >= MINSZ && slid[k] == l){
            int c = scls[k];
            if (c == 0) o0 = 1.f; else if (c == 1) o1 = 1.f; else if (c == 2) o2 = 1.f; else o3 = 1.f;
        }
    }
    out[p] = o0;
    out[NPIX + p] = o1;
    out[2*NPIX + p] = o2;
    out[3*NPIX + p] = o3;
}

// ---------------- launch ----------------
extern "C" void kernel_launch(void* const* d_in, const int* in_sizes, int n_in,
                              void* d_out, int out_size){
    const float *x = nullptr, *w1 = nullptr, *w2 = nullptr, *w3 = nullptr;
    const float *cw1 = nullptr, *cw2 = nullptr, *fc = nullptr;
    for (int i = 0; i < n_in; i++){
        switch (in_sizes[i]){
            case 4194304: x   = (const float*)d_in[i]; break;
            case 288:     w1  = (const float*)d_in[i]; break;
            case 9216:    w2  = (const float*)d_in[i]; break;
            case 32:      w3  = (const float*)d_in[i]; break;
            case 784:     cw1 = (const float*)d_in[i]; break;
            case 4608:    cw2 = (const float*)d_in[i]; break;
            case 128:     fc  = (const float*)d_in[i]; break;
            default: break;
        }
    }
    float* out = (float*)d_out;

    cudaFuncSetAttribute(k_conv123, cudaFuncAttributeMaxDynamicSharedMemorySize, CF_TOTAL);
    cudaFuncSetAttribute(k_cc, cudaFuncAttributeMaxDynamicSharedMemorySize, CC_SMEM);

    k_conv123<<<dim3(64,64), dim3(8,32), CF_TOTAL>>>(x, w1, w2, w3);

    int* la = nullptr; int* lb = nullptr;
    cudaGetSymbolAddress((void**)&la, g_labA);
    cudaGetSymbolAddress((void**)&lb, g_labB);
    for (int i = 0; i < 4; i++){
        k_cc<<<dim3(32,32), 1024, CC_SMEM>>>(la, lb);   // A -> B
        k_cc<<<dim3(32,32), 1024, CC_SMEM>>>(lb, la);   // B -> A
    }

    k_zero_counts<<<(NLBL+1023)/1024, 1024>>>();
    k_count<<<NPIX/256, 256>>>();
    k_topA<<<NBLK_TOP, 256>>>();
    k_topB<<<1, 256>>>();

    k_bbinit<<<1, 16>>>();
    k_bbox<<<NPIX/1024, 256>>>();

    k_roi<<<16, 256>>>(x);
    k_c1<<<802816/256, 256>>>(cw1);
    k_c2<<<373248/256, 256>>>(cw2);
    k_cls<<<16, 256>>>(fc);

    k_final<<<NPIX/256, 256>>>(out);
}